// round 2
// baseline (speedup 1.0000x reference)
#include <cuda_runtime.h>
#include <math.h>

#define NN 50000
#define NE 800000
#define KF 128          // IN_F
#define HF 128          // HEADS * OUT_F
#define NH 4
#define OF 32
#define EF 32

// ---------------- scratch (device globals: allocation-free) ----------------
__device__ float g_ht[(size_t)NN * HF];       // 25.6 MB
__device__ float g_ai[NN * NH];
__device__ float g_aj[NN * NH];
__device__ float g_e[(size_t)NE * NH];        // 12.8 MB raw scores
__device__ float g_eexp[(size_t)NE * NH];     // 12.8 MB e_exp in ROW-SORTED order
__device__ int   g_eid[NE];                   // sorted -> original edge id
__device__ int   g_ecol[NE];                  // sorted -> col (src node)
__device__ int   g_cnt[NN];
__device__ int   g_off[NN];
__device__ int   g_pos[NN];
__device__ float g_vc[NH * EF + NH];          // v[h][k] at h*32+k, c[h] at 128+h
__device__ unsigned int g_maxbits;

// orderable-uint encoding of float for atomicMax over mixed signs
__device__ __forceinline__ unsigned f2o(float x) {
    unsigned u = __float_as_uint(x);
    return (u & 0x80000000u) ? ~u : (u | 0x80000000u);
}
__device__ __forceinline__ float o2f(unsigned u) {
    return __uint_as_float((u & 0x80000000u) ? (u & 0x7fffffffu) : ~u);
}

// ---------------- kernel 0: init (zero counts, compute v/c, reset max) -----
__global__ void k_init(const float* __restrict__ eW, const float* __restrict__ a,
                       const float* __restrict__ eb) {
    int idx = blockIdx.x * blockDim.x + threadIdx.x;
    for (int i = idx; i < NN; i += gridDim.x * blockDim.x) g_cnt[i] = 0;
    if (blockIdx.x == 0) {
        int t = threadIdx.x;
        if (t < NH * EF) {                 // v[h][k] = sum_f eW[k, h*32+f] * a_e[h][f]
            int h = t >> 5, k = t & 31;
            float s = 0.0f;
            #pragma unroll
            for (int f = 0; f < OF; f++)
                s += eW[k * HF + h * OF + f] * a[h * 96 + 64 + f];
            g_vc[t] = s;
        } else if (t < NH * EF + NH) {     // c[h] = sum_f eb[h*32+f] * a_e[h][f]
            int h = t - NH * EF;
            float s = 0.0f;
            #pragma unroll
            for (int f = 0; f < OF; f++)
                s += eb[h * OF + f] * a[h * 96 + 64 + f];
            g_vc[NH * EF + h] = s;
        } else if (t == NH * EF + NH) {
            g_maxbits = 0u;                // < f2o(any float)
        }
    }
}

// ---------------- kernel 1: ht = h @ W, fused alpha_i/alpha_j epilogue -----
__global__ void k_gemm(const float* __restrict__ h, const float* __restrict__ W,
                       const float* __restrict__ a) {
    __shared__ float As[8][128];
    __shared__ float Bs[8][128];
    __shared__ float s_ai[512];   // [row(128)][head(4)]
    __shared__ float s_aj[512];
    int row0 = blockIdx.x * 128;
    int t = threadIdx.x;
    int tr = t >> 4;       // 0..15
    int tc = t & 15;       // 0..15
    s_ai[t] = 0.0f; s_ai[t + 256] = 0.0f;
    s_aj[t] = 0.0f; s_aj[t + 256] = 0.0f;

    float acc[8][8];
    #pragma unroll
    for (int i = 0; i < 8; i++)
        #pragma unroll
        for (int j = 0; j < 8; j++) acc[i][j] = 0.0f;

    for (int k0 = 0; k0 < KF; k0 += 8) {
        {
            int r = t >> 1;
            int kk = (t & 1) * 4;
            float4 hv = make_float4(0.f, 0.f, 0.f, 0.f);
            if (row0 + r < NN)
                hv = *(const float4*)(h + (size_t)(row0 + r) * KF + k0 + kk);
            As[kk + 0][r] = hv.x; As[kk + 1][r] = hv.y;
            As[kk + 2][r] = hv.z; As[kk + 3][r] = hv.w;
            int o = t * 4;
            *(float4*)(&Bs[0][0] + o) = *(const float4*)(W + (size_t)k0 * HF + o);
        }
        __syncthreads();
        #pragma unroll
        for (int k = 0; k < 8; k++) {
            float av[8], bv[8];
            *(float4*)(av)     = *(const float4*)&As[k][tr * 8];
            *(float4*)(av + 4) = *(const float4*)&As[k][tr * 8 + 4];
            *(float4*)(bv)     = *(const float4*)&Bs[k][tc * 8];
            *(float4*)(bv + 4) = *(const float4*)&Bs[k][tc * 8 + 4];
            #pragma unroll
            for (int i = 0; i < 8; i++)
                #pragma unroll
                for (int j = 0; j < 8; j++)
                    acc[i][j] += av[i] * bv[j];
        }
        __syncthreads();
    }

    // alpha weights for this thread's 8 columns (all within one head)
    int h0 = tc >> 2;                       // head of cols tc*8 .. tc*8+7
    float wi[8], wj[8];
    #pragma unroll
    for (int j = 0; j < 8; j++) {
        int cm = (tc * 8 + j) & 31;
        wi[j] = __ldg(&a[h0 * 96 + cm]);
        wj[j] = __ldg(&a[h0 * 96 + 32 + cm]);
    }

    #pragma unroll
    for (int i = 0; i < 8; i++) {
        int r = row0 + tr * 8 + i;
        float pi = 0.0f, pj = 0.0f;
        #pragma unroll
        for (int j = 0; j < 8; j++) {
            pi += acc[i][j] * wi[j];
            pj += acc[i][j] * wj[j];
        }
        int ridx = (tr * 8 + i) * 4 + h0;
        atomicAdd(&s_ai[ridx], pi);
        atomicAdd(&s_aj[ridx], pj);
        if (r < NN) {
            float4* dst = (float4*)(g_ht + (size_t)r * HF + tc * 8);
            dst[0] = make_float4(acc[i][0], acc[i][1], acc[i][2], acc[i][3]);
            dst[1] = make_float4(acc[i][4], acc[i][5], acc[i][6], acc[i][7]);
        }
    }
    __syncthreads();
    #pragma unroll
    for (int s = 0; s < 2; s++) {
        int u = t + s * 256;                // 0..511 = row(128) x head(4)
        int r = row0 + (u >> 2);
        if (r < NN) {
            g_ai[r * 4 + (u & 3)] = s_ai[u];
            g_aj[r * 4 + (u & 3)] = s_aj[u];
        }
    }
}

// ---------------- kernel 2: edge scores e + global max + row histogram -----
__global__ __launch_bounds__(256) void k_edge(const int* __restrict__ ei,
                                              const float* __restrict__ ea) {
    __shared__ float svc[NH * EF + NH];
    if (threadIdx.x < NH * EF + NH) svc[threadIdx.x] = g_vc[threadIdx.x];
    __syncthreads();

    int e = blockIdx.x * blockDim.x + threadIdx.x;
    float m = -1e30f;
    if (e < NE) {
        int row = ei[e];
        int col = ei[NE + e];
        float s0 = svc[128], s1 = svc[129], s2 = svc[130], s3 = svc[131];
        #pragma unroll
        for (int q = 0; q < 8; q++) {
            float4 x = *(const float4*)(ea + (size_t)e * EF + q * 4);
            int k = q * 4;
            s0 += x.x * svc[0*EF+k] + x.y * svc[0*EF+k+1] + x.z * svc[0*EF+k+2] + x.w * svc[0*EF+k+3];
            s1 += x.x * svc[1*EF+k] + x.y * svc[1*EF+k+1] + x.z * svc[1*EF+k+2] + x.w * svc[1*EF+k+3];
            s2 += x.x * svc[2*EF+k] + x.y * svc[2*EF+k+1] + x.z * svc[2*EF+k+2] + x.w * svc[2*EF+k+3];
            s3 += x.x * svc[3*EF+k] + x.y * svc[3*EF+k+1] + x.z * svc[3*EF+k+2] + x.w * svc[3*EF+k+3];
        }
        float4 ai = *(const float4*)(g_ai + (size_t)row * NH);
        float4 aj = *(const float4*)(g_aj + (size_t)col * NH);
        s0 += ai.x + aj.x; s1 += ai.y + aj.y; s2 += ai.z + aj.z; s3 += ai.w + aj.w;
        s0 = (s0 > 0.f) ? s0 : 0.2f * s0;
        s1 = (s1 > 0.f) ? s1 : 0.2f * s1;
        s2 = (s2 > 0.f) ? s2 : 0.2f * s2;
        s3 = (s3 > 0.f) ? s3 : 0.2f * s3;
        *(float4*)(g_e + (size_t)e * NH) = make_float4(s0, s1, s2, s3);
        m = fmaxf(fmaxf(s0, s1), fmaxf(s2, s3));
        atomicAdd(&g_cnt[row], 1);
    }
    // warp then block max -> one atomicMax per block
    #pragma unroll
    for (int o = 16; o; o >>= 1) m = fmaxf(m, __shfl_xor_sync(0xffffffffu, m, o));
    __shared__ float smax[8];
    if ((threadIdx.x & 31) == 0) smax[threadIdx.x >> 5] = m;
    __syncthreads();
    if (threadIdx.x == 0) {
        float bm = smax[0];
        #pragma unroll
        for (int w = 1; w < 8; w++) bm = fmaxf(bm, smax[w]);
        atomicMax(&g_maxbits, f2o(bm));
    }
}

// ---------------- kernel 3: exclusive scan of counts (single block) --------
__global__ void k_scan() {
    __shared__ int sp[1024];
    int t = threadIdx.x;
    const int CH = (NN + 1023) / 1024;   // 49
    int base = t * CH;
    int s = 0;
    for (int i = 0; i < CH; i++)
        if (base + i < NN) s += g_cnt[base + i];
    sp[t] = s;
    __syncthreads();
    for (int o = 1; o < 1024; o <<= 1) {
        int v = (t >= o) ? sp[t - o] : 0;
        __syncthreads();
        sp[t] += v;
        __syncthreads();
    }
    int run = sp[t] - s;   // exclusive prefix of this chunk
    for (int i = 0; i < CH; i++) {
        int n = base + i;
        if (n < NN) {
            g_off[n] = run;
            g_pos[n] = run;
            run += g_cnt[n];
        }
    }
}

// ---------------- kernel 4: place edges in row-sorted order + exp ----------
__global__ void k_place(const int* __restrict__ ei) {
    int e = blockIdx.x * blockDim.x + threadIdx.x;
    if (e >= NE) return;
    int row = ei[e];
    int col = ei[NE + e];
    int p = atomicAdd(&g_pos[row], 1);
    g_eid[p] = e;
    g_ecol[p] = col;
    float M = o2f(g_maxbits);
    float4 ev = *(const float4*)(g_e + (size_t)e * NH);
    ev.x = __expf(ev.x - M);
    ev.y = __expf(ev.y - M);
    ev.z = __expf(ev.z - M);
    ev.w = __expf(ev.w - M);
    *(float4*)(g_eexp + (size_t)p * NH) = ev;
}

// ---------------- kernel 5: per-node gather-reduce (denom, att, h_out+elu) -
__global__ __launch_bounds__(128) void k_nodes(float* __restrict__ out_h,
                                               float* __restrict__ out_att) {
    int n = blockIdx.x;
    int t = threadIdx.x;
    int start = g_off[n];
    int cnt = g_cnt[n];
    __shared__ float red[128];

    // denom per head: element i of segment has head i&3; thread t reads i≡t (mod 128)
    float s = 0.0f;
    for (int i = t; i < cnt * 4; i += 128) s += g_eexp[(size_t)start * 4 + i];
    red[t] = s;
    __syncthreads();
    #pragma unroll
    for (int o = 64; o >= 4; o >>= 1) {
        if (t < o) red[t] += red[t + o];
        __syncthreads();
    }
    int h = t >> 5;
    float invh = 1.0f / (red[h] + 1e-8f);
    float inv4 = (t < 4) ? 1.0f / (red[t] + 1e-8f) : 0.0f;
    __syncthreads();

    float acc = 0.0f;
    for (int k = 0; k < cnt; k++) {
        size_t idx = (size_t)(start + k);
        int col = g_ecol[idx];                                   // broadcast
        float w = g_eexp[idx * 4 + h] * invh;                    // broadcast per head group
        acc += w * g_ht[(size_t)col * HF + t];                   // coalesced 512B
        if (t < 4)
            out_att[(size_t)g_eid[idx] * 4 + t] = g_eexp[idx * 4 + t] * inv4;
    }
    out_h[(size_t)n * HF + t] = (acc > 0.0f) ? acc : expm1f(acc);
}

// ---------------- launcher --------------------------------------------------
extern "C" void kernel_launch(void* const* d_in, const int* in_sizes, int n_in,
                              void* d_out, int out_size) {
    (void)in_sizes; (void)n_in; (void)out_size;
    const float* h  = (const float*)d_in[0];
    const int*   ei = (const int*)d_in[1];
    const float* ea = (const float*)d_in[2];
    const float* W  = (const float*)d_in[3];
    const float* a  = (const float*)d_in[4];
    const float* eW = (const float*)d_in[5];
    const float* eb = (const float*)d_in[6];

    float* out_h   = (float*)d_out;                       // [NN, 128]
    float* out_att = (float*)d_out + (size_t)NN * HF;     // [NE, 4]

    k_init<<<200, 256>>>(eW, a, eb);
    k_gemm<<<(NN + 127) / 128, 256>>>(h, W, a);
    k_edge<<<(NE + 255) / 256, 256>>>(ei, ea);
    k_scan<<<1, 1024>>>();
    k_place<<<(NE + 255) / 256, 256>>>(ei);
    k_nodes<<<NN, 128>>>(out_h, out_att);
}

// round 3
// speedup vs baseline: 2.1628x; 2.1628x over previous
#include <cuda_runtime.h>
#include <math.h>

#define NN 50000
#define NE 800000
#define KF 128          // IN_F
#define HF 128          // HEADS * OUT_F
#define NH 4
#define OF 32
#define EF 32

// ---------------- scratch (device globals: allocation-free) ----------------
__device__ float g_ht[(size_t)NN * HF];                 // 25.6 MB
__device__ __align__(16) float g_ai[NN * NH];
__device__ __align__(16) float g_aj[NN * NH];
__device__ __align__(16) float g_e[(size_t)NE * NH];    // scores, then e_exp
__device__ __align__(16) float g_denom[NN * NH];
__device__ float g_vc[NH * EF + NH];                    // v[h][k] at h*32+k, c[h] at 128+h
__device__ unsigned int g_maxbits;

// orderable-uint encoding of float for atomicMax over mixed signs
__device__ __forceinline__ unsigned f2o(float x) {
    unsigned u = __float_as_uint(x);
    return (u & 0x80000000u) ? ~u : (u | 0x80000000u);
}
__device__ __forceinline__ float o2f(unsigned u) {
    return __uint_as_float((u & 0x80000000u) ? (u & 0x7fffffffu) : ~u);
}

// vectorized float atomic add (sm_90+): one RED.128 instead of 4 scalar REDs
__device__ __forceinline__ void red_add_v4(float* p, float x, float y, float z, float w) {
    asm volatile("red.global.add.v4.f32 [%0], {%1, %2, %3, %4};"
                 :: "l"(p), "f"(x), "f"(y), "f"(z), "f"(w) : "memory");
}

// ---------------- kernel 0: init (zero denom, compute v/c, reset max) -----
__global__ void k_init(const float* __restrict__ eW, const float* __restrict__ a,
                       const float* __restrict__ eb) {
    int idx = blockIdx.x * blockDim.x + threadIdx.x;
    for (int i = idx; i < NN * NH; i += gridDim.x * blockDim.x) g_denom[i] = 0.0f;
    if (blockIdx.x == 0) {
        int t = threadIdx.x;
        if (t < NH * EF) {                 // v[h][k] = sum_f eW[k, h*32+f] * a_e[h][f]
            int h = t >> 5, k = t & 31;
            float s = 0.0f;
            #pragma unroll
            for (int f = 0; f < OF; f++)
                s += eW[k * HF + h * OF + f] * a[h * 96 + 64 + f];
            g_vc[t] = s;
        } else if (t < NH * EF + NH) {     // c[h] = sum_f eb[h*32+f] * a_e[h][f]
            int h = t - NH * EF;
            float s = 0.0f;
            #pragma unroll
            for (int f = 0; f < OF; f++)
                s += eb[h * OF + f] * a[h * 96 + 64 + f];
            g_vc[NH * EF + h] = s;
        } else if (t == NH * EF + NH) {
            g_maxbits = 0u;                // < f2o(any float)
        }
    }
}

// ---------------- kernel 1: ht = h @ W, fused alpha_i/alpha_j epilogue -----
__global__ void k_gemm(const float* __restrict__ h, const float* __restrict__ W,
                       const float* __restrict__ a) {
    __shared__ float As[8][128];
    __shared__ float Bs[8][128];
    __shared__ float s_ai[512];   // [row(128)][head(4)]
    __shared__ float s_aj[512];
    int row0 = blockIdx.x * 128;
    int t = threadIdx.x;
    int tr = t >> 4;       // 0..15
    int tc = t & 15;       // 0..15
    s_ai[t] = 0.0f; s_ai[t + 256] = 0.0f;
    s_aj[t] = 0.0f; s_aj[t + 256] = 0.0f;

    float acc[8][8];
    #pragma unroll
    for (int i = 0; i < 8; i++)
        #pragma unroll
        for (int j = 0; j < 8; j++) acc[i][j] = 0.0f;

    for (int k0 = 0; k0 < KF; k0 += 8) {
        {
            int r = t >> 1;
            int kk = (t & 1) * 4;
            float4 hv = make_float4(0.f, 0.f, 0.f, 0.f);
            if (row0 + r < NN)
                hv = *(const float4*)(h + (size_t)(row0 + r) * KF + k0 + kk);
            As[kk + 0][r] = hv.x; As[kk + 1][r] = hv.y;
            As[kk + 2][r] = hv.z; As[kk + 3][r] = hv.w;
            int o = t * 4;
            *(float4*)(&Bs[0][0] + o) = *(const float4*)(W + (size_t)k0 * HF + o);
        }
        __syncthreads();
        #pragma unroll
        for (int k = 0; k < 8; k++) {
            float av[8], bv[8];
            *(float4*)(av)     = *(const float4*)&As[k][tr * 8];
            *(float4*)(av + 4) = *(const float4*)&As[k][tr * 8 + 4];
            *(float4*)(bv)     = *(const float4*)&Bs[k][tc * 8];
            *(float4*)(bv + 4) = *(const float4*)&Bs[k][tc * 8 + 4];
            #pragma unroll
            for (int i = 0; i < 8; i++)
                #pragma unroll
                for (int j = 0; j < 8; j++)
                    acc[i][j] += av[i] * bv[j];
        }
        __syncthreads();
    }

    // alpha weights for this thread's 8 columns (all within one head)
    int h0 = tc >> 2;                       // head of cols tc*8 .. tc*8+7
    float wi[8], wj[8];
    #pragma unroll
    for (int j = 0; j < 8; j++) {
        int cm = (tc * 8 + j) & 31;
        wi[j] = __ldg(&a[h0 * 96 + cm]);
        wj[j] = __ldg(&a[h0 * 96 + 32 + cm]);
    }

    #pragma unroll
    for (int i = 0; i < 8; i++) {
        int r = row0 + tr * 8 + i;
        float pi = 0.0f, pj = 0.0f;
        #pragma unroll
        for (int j = 0; j < 8; j++) {
            pi += acc[i][j] * wi[j];
            pj += acc[i][j] * wj[j];
        }
        int ridx = (tr * 8 + i) * 4 + h0;
        atomicAdd(&s_ai[ridx], pi);
        atomicAdd(&s_aj[ridx], pj);
        if (r < NN) {
            float4* dst = (float4*)(g_ht + (size_t)r * HF + tc * 8);
            dst[0] = make_float4(acc[i][0], acc[i][1], acc[i][2], acc[i][3]);
            dst[1] = make_float4(acc[i][4], acc[i][5], acc[i][6], acc[i][7]);
        }
    }
    __syncthreads();
    #pragma unroll
    for (int s = 0; s < 2; s++) {
        int u = t + s * 256;                // 0..511 = row(128) x head(4)
        int r = row0 + (u >> 2);
        if (r < NN) {
            g_ai[r * 4 + (u & 3)] = s_ai[u];
            g_aj[r * 4 + (u & 3)] = s_aj[u];
        }
    }
}

// ---------------- kernel 2: edge scores e + global max ---------------------
__global__ __launch_bounds__(256) void k_edge(const int* __restrict__ ei,
                                              const float* __restrict__ ea) {
    __shared__ float svc[NH * EF + NH];
    if (threadIdx.x < NH * EF + NH) svc[threadIdx.x] = g_vc[threadIdx.x];
    __syncthreads();

    int e = blockIdx.x * blockDim.x + threadIdx.x;
    float m = -1e30f;
    if (e < NE) {
        int row = ei[e];
        int col = ei[NE + e];
        float s0 = svc[128], s1 = svc[129], s2 = svc[130], s3 = svc[131];
        #pragma unroll
        for (int q = 0; q < 8; q++) {
            float4 x = *(const float4*)(ea + (size_t)e * EF + q * 4);
            int k = q * 4;
            s0 += x.x * svc[0*EF+k] + x.y * svc[0*EF+k+1] + x.z * svc[0*EF+k+2] + x.w * svc[0*EF+k+3];
            s1 += x.x * svc[1*EF+k] + x.y * svc[1*EF+k+1] + x.z * svc[1*EF+k+2] + x.w * svc[1*EF+k+3];
            s2 += x.x * svc[2*EF+k] + x.y * svc[2*EF+k+1] + x.z * svc[2*EF+k+2] + x.w * svc[2*EF+k+3];
            s3 += x.x * svc[3*EF+k] + x.y * svc[3*EF+k+1] + x.z * svc[3*EF+k+2] + x.w * svc[3*EF+k+3];
        }
        float4 ai = *(const float4*)(g_ai + (size_t)row * NH);
        float4 aj = *(const float4*)(g_aj + (size_t)col * NH);
        s0 += ai.x + aj.x; s1 += ai.y + aj.y; s2 += ai.z + aj.z; s3 += ai.w + aj.w;
        s0 = (s0 > 0.f) ? s0 : 0.2f * s0;
        s1 = (s1 > 0.f) ? s1 : 0.2f * s1;
        s2 = (s2 > 0.f) ? s2 : 0.2f * s2;
        s3 = (s3 > 0.f) ? s3 : 0.2f * s3;
        *(float4*)(g_e + (size_t)e * NH) = make_float4(s0, s1, s2, s3);
        m = fmaxf(fmaxf(s0, s1), fmaxf(s2, s3));
    }
    // warp then block max -> one atomicMax per block
    #pragma unroll
    for (int o = 16; o; o >>= 1) m = fmaxf(m, __shfl_xor_sync(0xffffffffu, m, o));
    __shared__ float smax[8];
    if ((threadIdx.x & 31) == 0) smax[threadIdx.x >> 5] = m;
    __syncthreads();
    if (threadIdx.x == 0) {
        float bm = smax[0];
        #pragma unroll
        for (int w = 1; w < 8; w++) bm = fmaxf(bm, smax[w]);
        atomicMax(&g_maxbits, f2o(bm));
    }
}

// ---------------- kernel 3: e_exp = exp(e - max), denom scatter (v4 RED) ---
__global__ __launch_bounds__(256) void k_expdenom(const int* __restrict__ ei) {
    int e = blockIdx.x * blockDim.x + threadIdx.x;
    if (e >= NE) return;
    float M = o2f(g_maxbits);
    int row = ei[e];
    float4 ev = *(float4*)(g_e + (size_t)e * NH);
    ev.x = __expf(ev.x - M);
    ev.y = __expf(ev.y - M);
    ev.z = __expf(ev.z - M);
    ev.w = __expf(ev.w - M);
    *(float4*)(g_e + (size_t)e * NH) = ev;
    red_add_v4(g_denom + (size_t)row * NH, ev.x, ev.y, ev.z, ev.w);
}

// ---------------- kernel 4: att + weighted scatter into h_out (v4 RED) -----
// one warp per edge; lane L handles floats 4L..4L+3 (head L>>3)
__global__ __launch_bounds__(256) void k_scatter(const int* __restrict__ ei,
                                                 float* __restrict__ out_h,
                                                 float* __restrict__ out_att) {
    int gw = (blockIdx.x * blockDim.x + threadIdx.x) >> 5;
    int lane = threadIdx.x & 31;
    if (gw >= NE) return;
    int e = gw;
    int row = ei[e];
    int col = ei[NE + e];

    float att = 0.0f;
    if (lane < NH) {
        float eexp = g_e[(size_t)e * NH + lane];
        float den = g_denom[(size_t)row * NH + lane];
        att = eexp / (den + 1e-8f);
        out_att[(size_t)e * NH + lane] = att;
    }
    float a_h = __shfl_sync(0xffffffffu, att, lane >> 3);
    float4 x = *(const float4*)(g_ht + (size_t)col * HF + lane * 4);
    red_add_v4(out_h + (size_t)row * HF + lane * 4,
               a_h * x.x, a_h * x.y, a_h * x.z, a_h * x.w);
}

// ---------------- kernel 5: elu in place -----------------------------------
__global__ void k_elu(float* __restrict__ out_h) {
    int i = blockIdx.x * blockDim.x + threadIdx.x;
    if (i < NN * HF) {
        float x = out_h[i];
        out_h[i] = (x > 0.0f) ? x : expm1f(x);
    }
}

// ---------------- launcher --------------------------------------------------
extern "C" void kernel_launch(void* const* d_in, const int* in_sizes, int n_in,
                              void* d_out, int out_size) {
    (void)in_sizes; (void)n_in; (void)out_size;
    const float* h  = (const float*)d_in[0];
    const int*   ei = (const int*)d_in[1];
    const float* ea = (const float*)d_in[2];
    const float* W  = (const float*)d_in[3];
    const float* a  = (const float*)d_in[4];
    const float* eW = (const float*)d_in[5];
    const float* eb = (const float*)d_in[6];

    float* out_h   = (float*)d_out;                       // [NN, 128]
    float* out_att = (float*)d_out + (size_t)NN * HF;     // [NE, 4]

    cudaMemsetAsync(out_h, 0, (size_t)NN * HF * sizeof(float), 0);

    k_init<<<200, 256>>>(eW, a, eb);
    k_gemm<<<(NN + 127) / 128, 256>>>(h, W, a);
    k_edge<<<(NE + 255) / 256, 256>>>(ei, ea);
    k_expdenom<<<(NE + 255) / 256, 256>>>(ei);
    k_scatter<<<(NE * 32 + 255) / 256, 256>>>(ei, out_h, out_att);
    k_elu<<<(NN * HF + 255) / 256, 256>>>(out_h);
}

// round 4
// speedup vs baseline: 2.8081x; 1.2984x over previous
#include <cuda_runtime.h>
#include <math.h>

#define NN 50000
#define NE 800000
#define KF 128          // IN_F
#define HF 128          // HEADS * OUT_F
#define NH 4
#define OF 32
#define EF 32
#define NBLK 196        // ceil(NN/256)

// ---------------- scratch (device globals: allocation-free) ----------------
__device__ float g_ht[(size_t)NN * HF];                 // 25.6 MB
__device__ __align__(16) float g_ai[NN * NH];
__device__ __align__(16) float g_aj[NN * NH];
__device__ __align__(16) float g_e[(size_t)NE * NH];    // raw scores
__device__ __align__(16) float g_eexp[(size_t)NE * NH]; // e_exp, ROW-SORTED
__device__ int   g_col[NE];                             // sorted -> col
__device__ int   g_eid[NE];                             // sorted -> edge id
__device__ int   g_cnt[NN];
__device__ int   g_pre[NN];                             // within-block excl prefix
__device__ int   g_off[NN];
__device__ int   g_pos[NN];
__device__ int   g_bsum[NBLK];
__device__ int   g_boff[NBLK];
__device__ float g_vc[NH * EF + NH];
__device__ unsigned int g_maxbits;

__device__ __forceinline__ unsigned f2o(float x) {
    unsigned u = __float_as_uint(x);
    return (u & 0x80000000u) ? ~u : (u | 0x80000000u);
}
__device__ __forceinline__ float o2f(unsigned u) {
    return __uint_as_float((u & 0x80000000u) ? (u & 0x7fffffffu) : ~u);
}

// ---------------- kernel 0: init (zero counts, compute v/c, reset max) -----
__global__ void k_init(const float* __restrict__ eW, const float* __restrict__ a,
                       const float* __restrict__ eb) {
    int idx = blockIdx.x * blockDim.x + threadIdx.x;
    for (int i = idx; i < NN; i += gridDim.x * blockDim.x) g_cnt[i] = 0;
    if (blockIdx.x == 0) {
        int t = threadIdx.x;
        if (t < NH * EF) {
            int h = t >> 5, k = t & 31;
            float s = 0.0f;
            #pragma unroll
            for (int f = 0; f < OF; f++)
                s += eW[k * HF + h * OF + f] * a[h * 96 + 64 + f];
            g_vc[t] = s;
        } else if (t < NH * EF + NH) {
            int h = t - NH * EF;
            float s = 0.0f;
            #pragma unroll
            for (int f = 0; f < OF; f++)
                s += eb[h * OF + f] * a[h * 96 + 64 + f];
            g_vc[NH * EF + h] = s;
        } else if (t == NH * EF + NH) {
            g_maxbits = 0u;
        }
    }
}

// ---------------- kernel 1: ht = h @ W, fused alpha_i/alpha_j epilogue -----
__global__ void k_gemm(const float* __restrict__ h, const float* __restrict__ W,
                       const float* __restrict__ a) {
    __shared__ float As[8][128];
    __shared__ float Bs[8][128];
    __shared__ float s_ai[512];   // [row(128)][head(4)]
    __shared__ float s_aj[512];
    int row0 = blockIdx.x * 128;
    int t = threadIdx.x;
    int tr = t >> 4;
    int tc = t & 15;
    s_ai[t] = 0.0f; s_ai[t + 256] = 0.0f;
    s_aj[t] = 0.0f; s_aj[t + 256] = 0.0f;

    float acc[8][8];
    #pragma unroll
    for (int i = 0; i < 8; i++)
        #pragma unroll
        for (int j = 0; j < 8; j++) acc[i][j] = 0.0f;

    for (int k0 = 0; k0 < KF; k0 += 8) {
        {
            int r = t >> 1;
            int kk = (t & 1) * 4;
            float4 hv = make_float4(0.f, 0.f, 0.f, 0.f);
            if (row0 + r < NN)
                hv = *(const float4*)(h + (size_t)(row0 + r) * KF + k0 + kk);
            As[kk + 0][r] = hv.x; As[kk + 1][r] = hv.y;
            As[kk + 2][r] = hv.z; As[kk + 3][r] = hv.w;
            int o = t * 4;
            *(float4*)(&Bs[0][0] + o) = *(const float4*)(W + (size_t)k0 * HF + o);
        }
        __syncthreads();
        #pragma unroll
        for (int k = 0; k < 8; k++) {
            float av[8], bv[8];
            *(float4*)(av)     = *(const float4*)&As[k][tr * 8];
            *(float4*)(av + 4) = *(const float4*)&As[k][tr * 8 + 4];
            *(float4*)(bv)     = *(const float4*)&Bs[k][tc * 8];
            *(float4*)(bv + 4) = *(const float4*)&Bs[k][tc * 8 + 4];
            #pragma unroll
            for (int i = 0; i < 8; i++)
                #pragma unroll
                for (int j = 0; j < 8; j++)
                    acc[i][j] += av[i] * bv[j];
        }
        __syncthreads();
    }

    int h0 = tc >> 2;
    float wi[8], wj[8];
    #pragma unroll
    for (int j = 0; j < 8; j++) {
        int cm = (tc * 8 + j) & 31;
        wi[j] = __ldg(&a[h0 * 96 + cm]);
        wj[j] = __ldg(&a[h0 * 96 + 32 + cm]);
    }

    #pragma unroll
    for (int i = 0; i < 8; i++) {
        int r = row0 + tr * 8 + i;
        float pi = 0.0f, pj = 0.0f;
        #pragma unroll
        for (int j = 0; j < 8; j++) {
            pi += acc[i][j] * wi[j];
            pj += acc[i][j] * wj[j];
        }
        int ridx = (tr * 8 + i) * 4 + h0;
        atomicAdd(&s_ai[ridx], pi);
        atomicAdd(&s_aj[ridx], pj);
        if (r < NN) {
            float4* dst = (float4*)(g_ht + (size_t)r * HF + tc * 8);
            dst[0] = make_float4(acc[i][0], acc[i][1], acc[i][2], acc[i][3]);
            dst[1] = make_float4(acc[i][4], acc[i][5], acc[i][6], acc[i][7]);
        }
    }
    __syncthreads();
    #pragma unroll
    for (int s = 0; s < 2; s++) {
        int u = t + s * 256;
        int r = row0 + (u >> 2);
        if (r < NN) {
            g_ai[r * 4 + (u & 3)] = s_ai[u];
            g_aj[r * 4 + (u & 3)] = s_aj[u];
        }
    }
}

// ---------------- kernel 2: edge scores + global max + row histogram -------
__global__ __launch_bounds__(256) void k_edge(const int* __restrict__ ei,
                                              const float* __restrict__ ea) {
    __shared__ float svc[NH * EF + NH];
    if (threadIdx.x < NH * EF + NH) svc[threadIdx.x] = g_vc[threadIdx.x];
    __syncthreads();

    int e = blockIdx.x * blockDim.x + threadIdx.x;
    float m = -1e30f;
    if (e < NE) {
        int row = ei[e];
        int col = ei[NE + e];
        float s0 = svc[128], s1 = svc[129], s2 = svc[130], s3 = svc[131];
        #pragma unroll
        for (int q = 0; q < 8; q++) {
            float4 x = *(const float4*)(ea + (size_t)e * EF + q * 4);
            int k = q * 4;
            s0 += x.x * svc[0*EF+k] + x.y * svc[0*EF+k+1] + x.z * svc[0*EF+k+2] + x.w * svc[0*EF+k+3];
            s1 += x.x * svc[1*EF+k] + x.y * svc[1*EF+k+1] + x.z * svc[1*EF+k+2] + x.w * svc[1*EF+k+3];
            s2 += x.x * svc[2*EF+k] + x.y * svc[2*EF+k+1] + x.z * svc[2*EF+k+2] + x.w * svc[2*EF+k+3];
            s3 += x.x * svc[3*EF+k] + x.y * svc[3*EF+k+1] + x.z * svc[3*EF+k+2] + x.w * svc[3*EF+k+3];
        }
        float4 ai = *(const float4*)(g_ai + (size_t)row * NH);
        float4 aj = *(const float4*)(g_aj + (size_t)col * NH);
        s0 += ai.x + aj.x; s1 += ai.y + aj.y; s2 += ai.z + aj.z; s3 += ai.w + aj.w;
        s0 = (s0 > 0.f) ? s0 : 0.2f * s0;
        s1 = (s1 > 0.f) ? s1 : 0.2f * s1;
        s2 = (s2 > 0.f) ? s2 : 0.2f * s2;
        s3 = (s3 > 0.f) ? s3 : 0.2f * s3;
        *(float4*)(g_e + (size_t)e * NH) = make_float4(s0, s1, s2, s3);
        m = fmaxf(fmaxf(s0, s1), fmaxf(s2, s3));
        atomicAdd(&g_cnt[row], 1);
    }
    #pragma unroll
    for (int o = 16; o; o >>= 1) m = fmaxf(m, __shfl_xor_sync(0xffffffffu, m, o));
    __shared__ float smax[8];
    if ((threadIdx.x & 31) == 0) smax[threadIdx.x >> 5] = m;
    __syncthreads();
    if (threadIdx.x == 0) {
        float bm = smax[0];
        #pragma unroll
        for (int w = 1; w < 8; w++) bm = fmaxf(bm, smax[w]);
        atomicMax(&g_maxbits, f2o(bm));
    }
}

// ---------------- scan stage 1: per-block exclusive prefix + block sums ----
__global__ __launch_bounds__(256) void k_scan1() {
    __shared__ int sh[256];
    int t = threadIdx.x;
    int i = blockIdx.x * 256 + t;
    int c = (i < NN) ? g_cnt[i] : 0;
    sh[t] = c;
    __syncthreads();
    #pragma unroll
    for (int o = 1; o < 256; o <<= 1) {
        int v = (t >= o) ? sh[t - o] : 0;
        __syncthreads();
        sh[t] += v;
        __syncthreads();
    }
    if (i < NN) g_pre[i] = sh[t] - c;
    if (t == 255) g_bsum[blockIdx.x] = sh[255];
}

// ---------------- scan stage 2: exclusive scan of 196 block sums -----------
__global__ __launch_bounds__(256) void k_scan2() {
    __shared__ int sh[256];
    int t = threadIdx.x;
    int c = (t < NBLK) ? g_bsum[t] : 0;
    sh[t] = c;
    __syncthreads();
    #pragma unroll
    for (int o = 1; o < 256; o <<= 1) {
        int v = (t >= o) ? sh[t - o] : 0;
        __syncthreads();
        sh[t] += v;
        __syncthreads();
    }
    if (t < NBLK) g_boff[t] = sh[t] - c;
}

// ---------------- scan stage 3: final offsets ------------------------------
__global__ __launch_bounds__(256) void k_scan3() {
    int i = blockIdx.x * 256 + threadIdx.x;
    if (i < NN) {
        int o = g_pre[i] + g_boff[blockIdx.x];
        g_off[i] = o;
        g_pos[i] = o;
    }
}

// ---------------- kernel 4: place edges row-sorted + exp -------------------
__global__ __launch_bounds__(256) void k_place(const int* __restrict__ ei) {
    int e = blockIdx.x * blockDim.x + threadIdx.x;
    if (e >= NE) return;
    int row = ei[e];
    int col = ei[NE + e];
    float M = o2f(g_maxbits);
    float4 ev = *(const float4*)(g_e + (size_t)e * NH);
    ev.x = __expf(ev.x - M);
    ev.y = __expf(ev.y - M);
    ev.z = __expf(ev.z - M);
    ev.w = __expf(ev.w - M);
    int p = atomicAdd(&g_pos[row], 1);
    *(float4*)(g_eexp + (size_t)p * NH) = ev;
    g_col[p] = col;
    g_eid[p] = e;
}

// ---------------- kernel 5: warp-per-node gather (denom, att, h_out, elu) --
__global__ __launch_bounds__(128) void k_nodes(float* __restrict__ out_h,
                                               float* __restrict__ out_att) {
    int n = blockIdx.x * 4 + (threadIdx.x >> 5);   // grid = NN/4 exactly
    int lane = threadIdx.x & 31;
    int start = g_off[n];
    int cnt = g_cnt[n];

    // denom per head: flattened eexp[start*4 .. +cnt*4); element i has head i&3;
    // lane covers i ≡ lane (mod 32) -> constant head lane&3
    float s = 0.0f;
    const float* ebase = g_eexp + (size_t)start * 4;
    for (int i = lane; i < cnt * 4; i += 32) s += ebase[i];
    s += __shfl_xor_sync(0xffffffffu, s, 4);
    s += __shfl_xor_sync(0xffffffffu, s, 8);
    s += __shfl_xor_sync(0xffffffffu, s, 16);
    float inv_h = 1.0f / (s + 1e-8f);                       // head = lane&3
    float my_inv = __shfl_sync(0xffffffffu, inv_h, lane >> 3); // head of my cols
    float i0 = __shfl_sync(0xffffffffu, inv_h, 0);
    float i1 = __shfl_sync(0xffffffffu, inv_h, 1);
    float i2 = __shfl_sync(0xffffffffu, inv_h, 2);
    float i3 = __shfl_sync(0xffffffffu, inv_h, 3);

    float4 acc = make_float4(0.f, 0.f, 0.f, 0.f);
    for (int k0 = 0; k0 < cnt; k0 += 32) {
        int k = k0 + lane;
        int mycol = 0;
        float4 me = make_float4(0.f, 0.f, 0.f, 0.f);
        if (k < cnt) {
            size_t idx = (size_t)(start + k);
            mycol = g_col[idx];
            me = *(const float4*)(g_eexp + idx * 4);
            int eid = g_eid[idx];
            *(float4*)(out_att + (size_t)eid * 4) =
                make_float4(me.x * i0, me.y * i1, me.z * i2, me.w * i3);
        }
        int lim = min(32, cnt - k0);
        #pragma unroll 4
        for (int j = 0; j < lim; j++) {
            int col  = __shfl_sync(0xffffffffu, mycol, j);
            float w0 = __shfl_sync(0xffffffffu, me.x, j);
            float w1 = __shfl_sync(0xffffffffu, me.y, j);
            float w2 = __shfl_sync(0xffffffffu, me.z, j);
            float w3 = __shfl_sync(0xffffffffu, me.w, j);
            float w = (lane < 16) ? ((lane < 8) ? w0 : w1)
                                  : ((lane < 24) ? w2 : w3);
            w *= my_inv;
            float4 x = *(const float4*)(g_ht + (size_t)col * HF + lane * 4);
            acc.x += w * x.x; acc.y += w * x.y;
            acc.z += w * x.z; acc.w += w * x.w;
        }
    }
    acc.x = (acc.x > 0.f) ? acc.x : expm1f(acc.x);
    acc.y = (acc.y > 0.f) ? acc.y : expm1f(acc.y);
    acc.z = (acc.z > 0.f) ? acc.z : expm1f(acc.z);
    acc.w = (acc.w > 0.f) ? acc.w : expm1f(acc.w);
    *(float4*)(out_h + (size_t)n * HF + lane * 4) = acc;
}

// ---------------- launcher --------------------------------------------------
extern "C" void kernel_launch(void* const* d_in, const int* in_sizes, int n_in,
                              void* d_out, int out_size) {
    (void)in_sizes; (void)n_in; (void)out_size;
    const float* h  = (const float*)d_in[0];
    const int*   ei = (const int*)d_in[1];
    const float* ea = (const float*)d_in[2];
    const float* W  = (const float*)d_in[3];
    const float* a  = (const float*)d_in[4];
    const float* eW = (const float*)d_in[5];
    const float* eb = (const float*)d_in[6];

    float* out_h   = (float*)d_out;                       // [NN, 128]
    float* out_att = (float*)d_out + (size_t)NN * HF;     // [NE, 4]

    k_init<<<200, 256>>>(eW, a, eb);
    k_gemm<<<(NN + 127) / 128, 256>>>(h, W, a);
    k_edge<<<(NE + 255) / 256, 256>>>(ei, ea);
    k_scan1<<<NBLK, 256>>>();
    k_scan2<<<1, 256>>>();
    k_scan3<<<NBLK, 256>>>();
    k_place<<<(NE + 255) / 256, 256>>>(ei);
    k_nodes<<<NN / 4, 128>>>(out_h, out_att);
}